// round 5
// baseline (speedup 1.0000x reference)
#include <cuda_runtime.h>
#include <math.h>

#define NB   8
#define NDIM 64
#define NH   128
#define NW   128
#define NPIX (NH * NW)     // 16384
#define NC2  256
#define NHID 128

// Global scratch
__device__ float g_u[(size_t)NB * NC2 * NPIX];    // project_in output
__device__ float g_g[(size_t)NB * NHID * NPIX];   // gated output
__device__ float g_Wd1[4 * 64 * 128];             // W_in  dup: [tile][k][2c]
__device__ float g_Wd3[128 * 128];                // W_out dup: [k][2o]

// ---- packed fp32x2 helpers ----
__device__ __forceinline__ void fma2(unsigned long long& d, unsigned long long a,
                                     unsigned long long b) {
    asm("fma.rn.f32x2 %0, %1, %2, %0;" : "+l"(d) : "l"(a), "l"(b));
}
__device__ __forceinline__ float2 up2(unsigned long long v) {
    float2 f;
    asm("mov.b64 {%0, %1}, %2;" : "=f"(f.x), "=f"(f.y) : "l"(v));
    return f;
}

// ============================================================================
// K0: duplicate weights into global scratch
// ============================================================================
__global__ void k_prep(const float* __restrict__ W_in,
                       const float* __restrict__ W_out) {
    int t = blockIdx.x * 256 + threadIdx.x;
    if (t < 4 * 64 * 64) {
        int tile = t >> 12, c = (t >> 6) & 63, k = t & 63;
        float w = W_in[(tile * 64 + c) * 64 + k];
        float2* p = (float2*)(g_Wd1 + (size_t)(tile * 64 + k) * 128 + 2 * c);
        *p = make_float2(w, w);
    }
    if (t < 64 * 128) {
        int o = t >> 7, k = t & 127;
        float w = W_out[o * 128 + k];
        float2* p = (float2*)(g_Wd3 + (size_t)k * 128 + 2 * o);
        *p = make_float2(w, w);
    }
}

// ============================================================================
// K1: project_in  u[b][c][p] = sum_k W_in[c][k] * x[b][k][p]
// Tile: 64 ch x 256 px, K=64. 256 threads, thread tile 8 ch x 8 px.
// Per k: 4 LDS.128 (bcast w, dup) + 2 LDS.128 (x) + 32 FFMA2.
// smem 96KB -> 2 blocks/SM.
// ============================================================================
__global__ __launch_bounds__(256, 2)
void k_proj_in(const float* __restrict__ x) {
    extern __shared__ float sm[];
    float* Wd = sm;            // [k=64][128]  (dup channels)  32KB
    float* Xs = sm + 8192;     // [k=64][256]  (pixels)        64KB

    const int p0  = blockIdx.x * 256;
    const int ct  = blockIdx.y;
    const int b   = blockIdx.z;
    const int tid = threadIdx.x;

    const float4* ws = (const float4*)(g_Wd1 + (size_t)ct * 8192);
    for (int l = tid; l < 2048; l += 256) ((float4*)Wd)[l] = ws[l];
    const float* xb = x + (size_t)b * NDIM * NPIX + p0;
    for (int l = tid; l < 64 * 64; l += 256) {
        int k = l >> 6, p4 = l & 63;
        ((float4*)(Xs + k * 256))[p4] = ((const float4*)(xb + (size_t)k * NPIX))[p4];
    }
    __syncthreads();

    const int pg = (tid & 31) * 8;   // pixel offset (8 px / thread)
    const int cg = (tid >> 5) * 8;   // channel offset (8 ch / thread)

    unsigned long long acc[8][4];
#pragma unroll
    for (int i = 0; i < 8; i++)
#pragma unroll
        for (int j = 0; j < 4; j++) acc[i][j] = 0ULL;

    const float* wb = Wd + 2 * cg;
    const float* xp = Xs + pg;

#pragma unroll 4
    for (int k = 0; k < 64; k++) {
        const ulonglong2* wp = (const ulonglong2*)(wb + k * 128);
        ulonglong2 w01 = wp[0], w23 = wp[1], w45 = wp[2], w67 = wp[3];
        ulonglong2 xA = *(const ulonglong2*)(xp + k * 256);
        ulonglong2 xB = *(const ulonglong2*)(xp + k * 256 + 4);
        fma2(acc[0][0], w01.x, xA.x); fma2(acc[0][1], w01.x, xA.y);
        fma2(acc[0][2], w01.x, xB.x); fma2(acc[0][3], w01.x, xB.y);
        fma2(acc[1][0], w01.y, xA.x); fma2(acc[1][1], w01.y, xA.y);
        fma2(acc[1][2], w01.y, xB.x); fma2(acc[1][3], w01.y, xB.y);
        fma2(acc[2][0], w23.x, xA.x); fma2(acc[2][1], w23.x, xA.y);
        fma2(acc[2][2], w23.x, xB.x); fma2(acc[2][3], w23.x, xB.y);
        fma2(acc[3][0], w23.y, xA.x); fma2(acc[3][1], w23.y, xA.y);
        fma2(acc[3][2], w23.y, xB.x); fma2(acc[3][3], w23.y, xB.y);
        fma2(acc[4][0], w45.x, xA.x); fma2(acc[4][1], w45.x, xA.y);
        fma2(acc[4][2], w45.x, xB.x); fma2(acc[4][3], w45.x, xB.y);
        fma2(acc[5][0], w45.y, xA.x); fma2(acc[5][1], w45.y, xA.y);
        fma2(acc[5][2], w45.y, xB.x); fma2(acc[5][3], w45.y, xB.y);
        fma2(acc[6][0], w67.x, xA.x); fma2(acc[6][1], w67.x, xA.y);
        fma2(acc[6][2], w67.x, xB.x); fma2(acc[6][3], w67.x, xB.y);
        fma2(acc[7][0], w67.y, xA.x); fma2(acc[7][1], w67.y, xA.y);
        fma2(acc[7][2], w67.y, xB.x); fma2(acc[7][3], w67.y, xB.y);
    }

    float* ub = g_u + ((size_t)(b * NC2 + ct * 64 + cg)) * NPIX + p0 + pg;
#pragma unroll
    for (int c = 0; c < 8; c++) {
        float2 a0 = up2(acc[c][0]), a1 = up2(acc[c][1]);
        float2 a2 = up2(acc[c][2]), a3 = up2(acc[c][3]);
        *(float4*)(ub + (size_t)c * NPIX)     = make_float4(a0.x, a0.y, a1.x, a1.y);
        *(float4*)(ub + (size_t)c * NPIX + 4) = make_float4(a2.x, a2.y, a3.x, a3.y);
    }
}

// ============================================================================
// K2: dynamic depthwise 3x3 (SAME) + exact-erf GELU gate
// 32 output rows per block, padded smem rows (stride 136).
// ============================================================================
#define SROW 136
__global__ __launch_bounds__(256)
void k_dwgate(const float* __restrict__ gen, const float* __restrict__ dwk,
              const float* __restrict__ lam) {
    __shared__ float s1[34 * SROW];
    __shared__ float s2[34 * SROW];

    const int r0  = blockIdx.x * 32;
    const int c   = blockIdx.y;
    const int b   = blockIdx.z;
    const int tid = threadIdx.x;

    float kk1[9], kk2[9];
    const float l1 = lam[c], l2 = lam[c + 128];
#pragma unroll
    for (int j = 0; j < 9; j++) {
        kk1[j] = dwk[c * 9 + j]         + l1 * gen[((size_t)b * NC2 + c) * 9 + j];
        kk2[j] = dwk[(c + 128) * 9 + j] + l2 * gen[((size_t)b * NC2 + c + 128) * 9 + j];
    }

    const float* u1 = g_u + ((size_t)b * NC2 + c) * NPIX;
    const float* u2 = u1 + (size_t)NHID * NPIX;

    for (int l = tid; l < 34 * 32; l += 256) {
        int rr = l >> 5, p4 = l & 31;
        int gy = r0 + rr - 1;
        float4 a  = make_float4(0.f, 0.f, 0.f, 0.f);
        float4 bb = a;
        if (gy >= 0 && gy < NH) {
            a  = ((const float4*)(u1 + (size_t)gy * NW))[p4];
            bb = ((const float4*)(u2 + (size_t)gy * NW))[p4];
        }
        ((float4*)(s1 + rr * SROW + 4))[p4] = a;
        ((float4*)(s2 + rr * SROW + 4))[p4] = bb;
    }
    if (tid < 68) {   // zero halo columns (x=-1 -> col 3, x=128 -> col 132)
        int rr = tid >> 1, col = (tid & 1) ? 132 : 3;
        s1[rr * SROW + col] = 0.f;
        s2[rr * SROW + col] = 0.f;
    }
    __syncthreads();

    float* gp = g_g + ((size_t)b * NHID + c) * NPIX + (size_t)r0 * NW;
#pragma unroll
    for (int i = 0; i < 16; i++) {
        int lp = tid + i * 256;
        int lr = lp >> 7;
        int xx = lp & 127;
        float a1 = 0.f, a2 = 0.f;
#pragma unroll
        for (int ky = 0; ky < 3; ky++) {
            const float* r1 = s1 + (lr + ky) * SROW + 4 + xx;
            const float* r2 = s2 + (lr + ky) * SROW + 4 + xx;
            a1 += kk1[ky * 3 + 0] * r1[-1] + kk1[ky * 3 + 1] * r1[0] + kk1[ky * 3 + 2] * r1[1];
            a2 += kk2[ky * 3 + 0] * r2[-1] + kk2[ky * 3 + 1] * r2[0] + kk2[ky * 3 + 2] * r2[1];
        }
        float ge = 0.5f * a1 * (1.0f + erff(a1 * 0.7071067811865475f));
        gp[lp] = ge * a2;
    }
}

// ============================================================================
// K3: project_out  out[b][o][p] = sum_c W_out[o][c] * g[b][c][p]
// Tile: 64 out x 256 px, K=128 in two 64-chunks. 256 threads, 8x8 thread tile.
// smem 96KB -> 2 blocks/SM.
// ============================================================================
__global__ __launch_bounds__(256, 2)
void k_proj_out(float* __restrict__ out) {
    extern __shared__ float sm[];
    float* Wd = sm;            // [k=64][128] dup (per chunk)   32KB
    float* Xs = sm + 8192;     // [k=64][256]                   64KB

    const int p0  = blockIdx.x * 256;
    const int b   = blockIdx.y;
    const int tid = threadIdx.x;

    const int pg = (tid & 31) * 8;
    const int og = (tid >> 5) * 8;

    unsigned long long acc[8][4];
#pragma unroll
    for (int i = 0; i < 8; i++)
#pragma unroll
        for (int j = 0; j < 4; j++) acc[i][j] = 0ULL;

    const float* wb = Wd + 2 * og;
    const float* xp = Xs + pg;

    for (int kc = 0; kc < 2; kc++) {
        const float4* ws = (const float4*)(g_Wd3 + (size_t)kc * 8192);
        for (int l = tid; l < 2048; l += 256) ((float4*)Wd)[l] = ws[l];
        const float* gb = g_g + ((size_t)b * NHID + kc * 64) * NPIX + p0;
        for (int l = tid; l < 64 * 64; l += 256) {
            int k = l >> 6, p4 = l & 63;
            ((float4*)(Xs + k * 256))[p4] =
                ((const float4*)(gb + (size_t)k * NPIX))[p4];
        }
        __syncthreads();

#pragma unroll 4
        for (int k = 0; k < 64; k++) {
            const ulonglong2* wp = (const ulonglong2*)(wb + k * 128);
            ulonglong2 w01 = wp[0], w23 = wp[1], w45 = wp[2], w67 = wp[3];
            ulonglong2 xA = *(const ulonglong2*)(xp + k * 256);
            ulonglong2 xB = *(const ulonglong2*)(xp + k * 256 + 4);
            fma2(acc[0][0], w01.x, xA.x); fma2(acc[0][1], w01.x, xA.y);
            fma2(acc[0][2], w01.x, xB.x); fma2(acc[0][3], w01.x, xB.y);
            fma2(acc[1][0], w01.y, xA.x); fma2(acc[1][1], w01.y, xA.y);
            fma2(acc[1][2], w01.y, xB.x); fma2(acc[1][3], w01.y, xB.y);
            fma2(acc[2][0], w23.x, xA.x); fma2(acc[2][1], w23.x, xA.y);
            fma2(acc[2][2], w23.x, xB.x); fma2(acc[2][3], w23.x, xB.y);
            fma2(acc[3][0], w23.y, xA.x); fma2(acc[3][1], w23.y, xA.y);
            fma2(acc[3][2], w23.y, xB.x); fma2(acc[3][3], w23.y, xB.y);
            fma2(acc[4][0], w45.x, xA.x); fma2(acc[4][1], w45.x, xA.y);
            fma2(acc[4][2], w45.x, xB.x); fma2(acc[4][3], w45.x, xB.y);
            fma2(acc[5][0], w45.y, xA.x); fma2(acc[5][1], w45.y, xA.y);
            fma2(acc[5][2], w45.y, xB.x); fma2(acc[5][3], w45.y, xB.y);
            fma2(acc[6][0], w67.x, xA.x); fma2(acc[6][1], w67.x, xA.y);
            fma2(acc[6][2], w67.x, xB.x); fma2(acc[6][3], w67.x, xB.y);
            fma2(acc[7][0], w67.y, xA.x); fma2(acc[7][1], w67.y, xA.y);
            fma2(acc[7][2], w67.y, xB.x); fma2(acc[7][3], w67.y, xB.y);
        }
        __syncthreads();
    }

    float* ob = out + ((size_t)(b * NDIM + og)) * NPIX + p0 + pg;
#pragma unroll
    for (int o = 0; o < 8; o++) {
        float2 a0 = up2(acc[o][0]), a1 = up2(acc[o][1]);
        float2 a2 = up2(acc[o][2]), a3 = up2(acc[o][3]);
        *(float4*)(ob + (size_t)o * NPIX)     = make_float4(a0.x, a0.y, a1.x, a1.y);
        *(float4*)(ob + (size_t)o * NPIX + 4) = make_float4(a2.x, a2.y, a3.x, a3.y);
    }
}

// ============================================================================
extern "C" void kernel_launch(void* const* d_in, const int* in_sizes, int n_in,
                              void* d_out, int out_size) {
    const float* x     = (const float*)d_in[0];
    const float* gen   = (const float*)d_in[1];
    const float* W_in  = (const float*)d_in[2];
    const float* dwk   = (const float*)d_in[3];
    const float* lam   = (const float*)d_in[4];
    const float* W_out = (const float*)d_in[5];
    float* out = (float*)d_out;

    const int smem = 96 * 1024;
    cudaFuncSetAttribute(k_proj_in,  cudaFuncAttributeMaxDynamicSharedMemorySize, smem);
    cudaFuncSetAttribute(k_proj_out, cudaFuncAttributeMaxDynamicSharedMemorySize, smem);

    k_prep<<<64, 256>>>(W_in, W_out);
    k_proj_in<<<dim3(NPIX / 256, NC2 / 64, NB), 256, smem>>>(x);
    k_dwgate<<<dim3(NH / 32, NHID, NB), 256>>>(gen, dwk, lam);
    k_proj_out<<<dim3(NPIX / 256, NB), 256, smem>>>(out);
}

// round 7
// speedup vs baseline: 1.2908x; 1.2908x over previous
#include <cuda_runtime.h>
#include <math.h>

#define NB   8
#define NDIM 64
#define NH   128
#define NW   128
#define NPIX (NH * NW)     // 16384
#define NC2  256
#define NHID 128

// Global scratch
__device__ float g_u[(size_t)NB * NC2 * NPIX];    // project_in output
__device__ float g_g[(size_t)NB * NHID * NPIX];   // gated output
__device__ float g_Wt1[4 * 64 * 64];              // W_in  transposed: [tile][k][c]
__device__ float g_Wt3[2 * 64 * 64];              // W_out transposed: [kchunk][k][o]

// ---- packed fp32x2 helpers ----
__device__ __forceinline__ unsigned long long pk2(float v) {
    unsigned long long r;
    asm("mov.b64 %0, {%1, %1};" : "=l"(r) : "f"(v));
    return r;
}
__device__ __forceinline__ void fma2(unsigned long long& d, unsigned long long a,
                                     unsigned long long b) {
    asm("fma.rn.f32x2 %0, %1, %2, %0;" : "+l"(d) : "l"(a), "l"(b));
}
__device__ __forceinline__ float2 up2(unsigned long long v) {
    float2 f;
    asm("mov.b64 {%0, %1}, %2;" : "=f"(f.x), "=f"(f.y) : "l"(v));
    return f;
}

// ============================================================================
// K0: transpose weights into [k][c] layout (non-duplicated)
// ============================================================================
__global__ void k_prep(const float* __restrict__ W_in,
                       const float* __restrict__ W_out) {
    int t = blockIdx.x * 256 + threadIdx.x;
    if (t < 4 * 64 * 64) {                       // g_Wt1[tile][k][c]
        int tile = t >> 12, c = (t >> 6) & 63, k = t & 63;
        g_Wt1[(size_t)tile * 4096 + k * 64 + c] = W_in[(tile * 64 + c) * 64 + k];
    }
    if (t < 2 * 64 * 64) {                       // g_Wt3[kc][kk][o]
        int kc = t >> 12, o = (t >> 6) & 63, kk = t & 63;
        g_Wt3[(size_t)kc * 4096 + kk * 64 + o] = W_out[o * 128 + kc * 64 + kk];
    }
}

// ============================================================================
// K1: project_in  u[b][c][p] = sum_k W_in[c][k] * x[b][k][p]
// Tile: 64 ch x 128 px, K=64. 256 threads; thread tile 8 ch (4 packed pairs) x 4 px.
// Channel-packed accumulators: per k only 3 LDS.128 (2 w + 1 x) + 4 dup-MOVs
// + 16 FFMA2  -> crossbar cap 66% (vs 40% pixel-packed).
// smem 48KB -> 3 blocks/SM (reg-limited).
// ============================================================================
__global__ __launch_bounds__(256, 3)
void k_proj_in(const float* __restrict__ x) {
    extern __shared__ float sm[];
    float* Wt = sm;            // [k=64][c=64]   16KB
    float* Xs = sm + 4096;     // [k=64][p=128]  32KB

    const int p0  = blockIdx.x * 128;
    const int ct  = blockIdx.y;
    const int b   = blockIdx.z;
    const int tid = threadIdx.x;

    const float4* ws = (const float4*)(g_Wt1 + (size_t)ct * 4096);
    for (int l = tid; l < 1024; l += 256) ((float4*)Wt)[l] = ws[l];
    const float* xb = x + (size_t)b * NDIM * NPIX + p0;
    for (int l = tid; l < 64 * 32; l += 256) {
        int k = l >> 5, p4 = l & 31;
        ((float4*)(Xs + k * 128))[p4] = ((const float4*)(xb + (size_t)k * NPIX))[p4];
    }
    __syncthreads();

    const int pg = (tid & 31) * 4;   // 4 px / thread
    const int cg = (tid >> 5) * 8;   // 8 ch / thread (warp-uniform)

    unsigned long long acc[4][4];    // [ch-pair][px]
#pragma unroll
    for (int i = 0; i < 4; i++)
#pragma unroll
        for (int j = 0; j < 4; j++) acc[i][j] = 0ULL;

    const float* wb = Wt + cg;
    const float* xp = Xs + pg;

#pragma unroll 8
    for (int k = 0; k < 64; k++) {
        const ulonglong2* wp = (const ulonglong2*)(wb + k * 64);
        ulonglong2 wA = wp[0], wB = wp[1];      // (c0,c1)(c2,c3) | (c4,c5)(c6,c7)
        float4 xv = *(const float4*)(xp + k * 128);
        unsigned long long x0 = pk2(xv.x), x1 = pk2(xv.y);
        unsigned long long x2 = pk2(xv.z), x3 = pk2(xv.w);
        fma2(acc[0][0], wA.x, x0); fma2(acc[0][1], wA.x, x1);
        fma2(acc[0][2], wA.x, x2); fma2(acc[0][3], wA.x, x3);
        fma2(acc[1][0], wA.y, x0); fma2(acc[1][1], wA.y, x1);
        fma2(acc[1][2], wA.y, x2); fma2(acc[1][3], wA.y, x3);
        fma2(acc[2][0], wB.x, x0); fma2(acc[2][1], wB.x, x1);
        fma2(acc[2][2], wB.x, x2); fma2(acc[2][3], wB.x, x3);
        fma2(acc[3][0], wB.y, x0); fma2(acc[3][1], wB.y, x1);
        fma2(acc[3][2], wB.y, x2); fma2(acc[3][3], wB.y, x3);
    }

    float* ub = g_u + ((size_t)(b * NC2 + ct * 64 + cg)) * NPIX + p0 + pg;
#pragma unroll
    for (int j = 0; j < 4; j++) {
        float2 v0 = up2(acc[j][0]), v1 = up2(acc[j][1]);
        float2 v2 = up2(acc[j][2]), v3 = up2(acc[j][3]);
        *(float4*)(ub + (size_t)(2 * j) * NPIX)     = make_float4(v0.x, v1.x, v2.x, v3.x);
        *(float4*)(ub + (size_t)(2 * j + 1) * NPIX) = make_float4(v0.y, v1.y, v2.y, v3.y);
    }
}

// ============================================================================
// K2: dynamic depthwise 3x3 (SAME) + exact-erf GELU gate
// 32 output rows per block, padded smem rows (stride 136).
// ============================================================================
#define SROW 136
__global__ __launch_bounds__(256)
void k_dwgate(const float* __restrict__ gen, const float* __restrict__ dwk,
              const float* __restrict__ lam) {
    __shared__ float s1[34 * SROW];
    __shared__ float s2[34 * SROW];

    const int r0  = blockIdx.x * 32;
    const int c   = blockIdx.y;
    const int b   = blockIdx.z;
    const int tid = threadIdx.x;

    float kk1[9], kk2[9];
    const float l1 = lam[c], l2 = lam[c + 128];
#pragma unroll
    for (int j = 0; j < 9; j++) {
        kk1[j] = dwk[c * 9 + j]         + l1 * gen[((size_t)b * NC2 + c) * 9 + j];
        kk2[j] = dwk[(c + 128) * 9 + j] + l2 * gen[((size_t)b * NC2 + c + 128) * 9 + j];
    }

    const float* u1 = g_u + ((size_t)b * NC2 + c) * NPIX;
    const float* u2 = u1 + (size_t)NHID * NPIX;

    for (int l = tid; l < 34 * 32; l += 256) {
        int rr = l >> 5, p4 = l & 31;
        int gy = r0 + rr - 1;
        float4 a  = make_float4(0.f, 0.f, 0.f, 0.f);
        float4 bb = a;
        if (gy >= 0 && gy < NH) {
            a  = ((const float4*)(u1 + (size_t)gy * NW))[p4];
            bb = ((const float4*)(u2 + (size_t)gy * NW))[p4];
        }
        ((float4*)(s1 + rr * SROW + 4))[p4] = a;
        ((float4*)(s2 + rr * SROW + 4))[p4] = bb;
    }
    if (tid < 68) {   // zero halo columns (x=-1 -> col 3, x=128 -> col 132)
        int rr = tid >> 1, col = (tid & 1) ? 132 : 3;
        s1[rr * SROW + col] = 0.f;
        s2[rr * SROW + col] = 0.f;
    }
    __syncthreads();

    float* gp = g_g + ((size_t)b * NHID + c) * NPIX + (size_t)r0 * NW;
#pragma unroll
    for (int i = 0; i < 16; i++) {
        int lp = tid + i * 256;
        int lr = lp >> 7;
        int xx = lp & 127;
        float a1 = 0.f, a2 = 0.f;
#pragma unroll
        for (int ky = 0; ky < 3; ky++) {
            const float* r1 = s1 + (lr + ky) * SROW + 4 + xx;
            const float* r2 = s2 + (lr + ky) * SROW + 4 + xx;
            a1 += kk1[ky * 3 + 0] * r1[-1] + kk1[ky * 3 + 1] * r1[0] + kk1[ky * 3 + 2] * r1[1];
            a2 += kk2[ky * 3 + 0] * r2[-1] + kk2[ky * 3 + 1] * r2[0] + kk2[ky * 3 + 2] * r2[1];
        }
        float ge = 0.5f * a1 * (1.0f + erff(a1 * 0.7071067811865475f));
        gp[lp] = ge * a2;
    }
}

// ============================================================================
// K3: project_out  out[b][o][p] = sum_c W_out[o][c] * g[b][c][p]
// Tile: 64 out x 128 px, K=128 in two 64-chunks. Channel-packed acc.
// smem 48KB -> 3 blocks/SM.
// ============================================================================
__global__ __launch_bounds__(256, 3)
void k_proj_out(float* __restrict__ out) {
    extern __shared__ float sm[];
    float* Wt = sm;            // [k=64][o=64] per chunk  16KB
    float* Xs = sm + 4096;     // [k=64][p=128]           32KB

    const int p0  = blockIdx.x * 128;
    const int b   = blockIdx.y;
    const int tid = threadIdx.x;

    const int pg = (tid & 31) * 4;
    const int og = (tid >> 5) * 8;

    unsigned long long acc[4][4];
#pragma unroll
    for (int i = 0; i < 4; i++)
#pragma unroll
        for (int j = 0; j < 4; j++) acc[i][j] = 0ULL;

    const float* wb = Wt + og;
    const float* xp = Xs + pg;

    for (int kc = 0; kc < 2; kc++) {
        const float4* ws = (const float4*)(g_Wt3 + (size_t)kc * 4096);
        for (int l = tid; l < 1024; l += 256) ((float4*)Wt)[l] = ws[l];
        const float* gb = g_g + ((size_t)b * NHID + kc * 64) * NPIX + p0;
        for (int l = tid; l < 64 * 32; l += 256) {
            int k = l >> 5, p4 = l & 31;
            ((float4*)(Xs + k * 128))[p4] =
                ((const float4*)(gb + (size_t)k * NPIX))[p4];
        }
        __syncthreads();

#pragma unroll 8
        for (int k = 0; k < 64; k++) {
            const ulonglong2* wp = (const ulonglong2*)(wb + k * 64);
            ulonglong2 wA = wp[0], wB = wp[1];
            float4 xv = *(const float4*)(xp + k * 128);
            unsigned long long x0 = pk2(xv.x), x1 = pk2(xv.y);
            unsigned long long x2 = pk2(xv.z), x3 = pk2(xv.w);
            fma2(acc[0][0], wA.x, x0); fma2(acc[0][1], wA.x, x1);
            fma2(acc[0][2], wA.x, x2); fma2(acc[0][3], wA.x, x3);
            fma2(acc[1][0], wA.y, x0); fma2(acc[1][1], wA.y, x1);
            fma2(acc[1][2], wA.y, x2); fma2(acc[1][3], wA.y, x3);
            fma2(acc[2][0], wB.x, x0); fma2(acc[2][1], wB.x, x1);
            fma2(acc[2][2], wB.x, x2); fma2(acc[2][3], wB.x, x3);
            fma2(acc[3][0], wB.y, x0); fma2(acc[3][1], wB.y, x1);
            fma2(acc[3][2], wB.y, x2); fma2(acc[3][3], wB.y, x3);
        }
        __syncthreads();
    }

    float* ob = out + ((size_t)(b * NDIM + og)) * NPIX + p0 + pg;
#pragma unroll
    for (int j = 0; j < 4; j++) {
        float2 v0 = up2(acc[j][0]), v1 = up2(acc[j][1]);
        float2 v2 = up2(acc[j][2]), v3 = up2(acc[j][3]);
        *(float4*)(ob + (size_t)(2 * j) * NPIX)     = make_float4(v0.x, v1.x, v2.x, v3.x);
        *(float4*)(ob + (size_t)(2 * j + 1) * NPIX) = make_float4(v0.y, v1.y, v2.y, v3.y);
    }
}

// ============================================================================
extern "C" void kernel_launch(void* const* d_in, const int* in_sizes, int n_in,
                              void* d_out, int out_size) {
    const float* x     = (const float*)d_in[0];
    const float* gen   = (const float*)d_in[1];
    const float* W_in  = (const float*)d_in[2];
    const float* dwk   = (const float*)d_in[3];
    const float* lam   = (const float*)d_in[4];
    const float* W_out = (const float*)d_in[5];
    float* out = (float*)d_out;

    const int smem = 48 * 1024;
    cudaFuncSetAttribute(k_proj_in,  cudaFuncAttributeMaxDynamicSharedMemorySize, smem);
    cudaFuncSetAttribute(k_proj_out, cudaFuncAttributeMaxDynamicSharedMemorySize, smem);

    k_prep<<<64, 256>>>(W_in, W_out);
    k_proj_in<<<dim3(NPIX / 128, NC2 / 64, NB), 256, smem>>>(x);
    k_dwgate<<<dim3(NH / 32, NHID, NB), 256>>>(gen, dwk, lam);
    k_proj_out<<<dim3(NPIX / 128, NB), 256, smem>>>(out);
}

// round 12
// speedup vs baseline: 1.3434x; 1.0408x over previous
#include <cuda_runtime.h>
#include <math.h>

#define NB   8
#define NDIM 64
#define NH   128
#define NW   128
#define NPIX (NH * NW)     // 16384
#define NC2  256
#define NHID 128

// Global scratch
__device__ float g_u[(size_t)NB * NC2 * NPIX];    // project_in output
__device__ float g_g[(size_t)NB * NHID * NPIX];   // gated output
__device__ float g_Wt1[4 * 64 * 64];              // W_in  transposed: [tile][k][c]
__device__ float g_Wt3[2 * 64 * 64];              // W_out transposed: [kchunk][k][o]

// ---- packed fp32x2 helpers ----
__device__ __forceinline__ unsigned long long pk2(float v) {
    unsigned long long r;
    asm("mov.b64 %0, {%1, %1};" : "=l"(r) : "f"(v));
    return r;
}
__device__ __forceinline__ void fma2(unsigned long long& d, unsigned long long a,
                                     unsigned long long b) {
    asm("fma.rn.f32x2 %0, %1, %2, %0;" : "+l"(d) : "l"(a), "l"(b));
}
__device__ __forceinline__ float2 up2(unsigned long long v) {
    float2 f;
    asm("mov.b64 {%0, %1}, %2;" : "=f"(f.x), "=f"(f.y) : "l"(v));
    return f;
}

// ============================================================================
// K0: transpose weights into [k][c] layout (non-duplicated)
// ============================================================================
__global__ void k_prep(const float* __restrict__ W_in,
                       const float* __restrict__ W_out) {
    int t = blockIdx.x * 256 + threadIdx.x;
    if (t < 4 * 64 * 64) {                       // g_Wt1[tile][k][c]
        int tile = t >> 12, c = (t >> 6) & 63, k = t & 63;
        g_Wt1[(size_t)tile * 4096 + k * 64 + c] = W_in[(tile * 64 + c) * 64 + k];
    }
    if (t < 2 * 64 * 64) {                       // g_Wt3[kc][kk][o]
        int kc = t >> 12, o = (t >> 6) & 63, kk = t & 63;
        g_Wt3[(size_t)kc * 4096 + kk * 64 + o] = W_out[o * 128 + kc * 64 + kk];
    }
}

// ============================================================================
// K1: project_in  u[b][c][p] = sum_k W_in[c][k] * x[b][k][p]
// Tile: 64 ch x 128 px, K=64. 256 threads; thread tile 8 ch (4 packed pairs) x 4 px.
// Channel-packed accumulators: per k 3 LDS.128 (2 w bcast + 1 x) + 4 dup-MOVs
// + 16 FFMA2.  __launch_bounds__(256,4): 64-reg target -> 4 blocks/SM (67% occ).
// ============================================================================
__global__ __launch_bounds__(256, 4)
void k_proj_in(const float* __restrict__ x) {
    extern __shared__ float sm[];
    float* Wt = sm;            // [k=64][c=64]   16KB
    float* Xs = sm + 4096;     // [k=64][p=128]  32KB

    const int p0  = blockIdx.x * 128;
    const int ct  = blockIdx.y;
    const int b   = blockIdx.z;
    const int tid = threadIdx.x;

    const float4* ws = (const float4*)(g_Wt1 + (size_t)ct * 4096);
    for (int l = tid; l < 1024; l += 256) ((float4*)Wt)[l] = ws[l];
    const float* xb = x + (size_t)b * NDIM * NPIX + p0;
    for (int l = tid; l < 64 * 32; l += 256) {
        int k = l >> 5, p4 = l & 31;
        ((float4*)(Xs + k * 128))[p4] = ((const float4*)(xb + (size_t)k * NPIX))[p4];
    }
    __syncthreads();

    const int pg = (tid & 31) * 4;   // 4 px / thread
    const int cg = (tid >> 5) * 8;   // 8 ch / thread (warp-uniform)

    unsigned long long acc[4][4];    // [ch-pair][px]
#pragma unroll
    for (int i = 0; i < 4; i++)
#pragma unroll
        for (int j = 0; j < 4; j++) acc[i][j] = 0ULL;

    const float* wb = Wt + cg;
    const float* xp = Xs + pg;

#pragma unroll 8
    for (int k = 0; k < 64; k++) {
        const ulonglong2* wp = (const ulonglong2*)(wb + k * 64);
        ulonglong2 wA = wp[0], wB = wp[1];      // (c0,c1)(c2,c3) | (c4,c5)(c6,c7)
        float4 xv = *(const float4*)(xp + k * 128);
        unsigned long long x0 = pk2(xv.x), x1 = pk2(xv.y);
        unsigned long long x2 = pk2(xv.z), x3 = pk2(xv.w);
        fma2(acc[0][0], wA.x, x0); fma2(acc[0][1], wA.x, x1);
        fma2(acc[0][2], wA.x, x2); fma2(acc[0][3], wA.x, x3);
        fma2(acc[1][0], wA.y, x0); fma2(acc[1][1], wA.y, x1);
        fma2(acc[1][2], wA.y, x2); fma2(acc[1][3], wA.y, x3);
        fma2(acc[2][0], wB.x, x0); fma2(acc[2][1], wB.x, x1);
        fma2(acc[2][2], wB.x, x2); fma2(acc[2][3], wB.x, x3);
        fma2(acc[3][0], wB.y, x0); fma2(acc[3][1], wB.y, x1);
        fma2(acc[3][2], wB.y, x2); fma2(acc[3][3], wB.y, x3);
    }

    float* ub = g_u + ((size_t)(b * NC2 + ct * 64 + cg)) * NPIX + p0 + pg;
#pragma unroll
    for (int j = 0; j < 4; j++) {
        float2 v0 = up2(acc[j][0]), v1 = up2(acc[j][1]);
        float2 v2 = up2(acc[j][2]), v3 = up2(acc[j][3]);
        *(float4*)(ub + (size_t)(2 * j) * NPIX)     = make_float4(v0.x, v1.x, v2.x, v3.x);
        *(float4*)(ub + (size_t)(2 * j + 1) * NPIX) = make_float4(v0.y, v1.y, v2.y, v3.y);
    }
}

// ============================================================================
// K2: dynamic depthwise 3x3 (SAME) + exact-erf GELU gate
// 32 output rows per block, padded smem rows (stride 136).
// ============================================================================
#define SROW 136
__global__ __launch_bounds__(256)
void k_dwgate(const float* __restrict__ gen, const float* __restrict__ dwk,
              const float* __restrict__ lam) {
    __shared__ float s1[34 * SROW];
    __shared__ float s2[34 * SROW];

    const int r0  = blockIdx.x * 32;
    const int c   = blockIdx.y;
    const int b   = blockIdx.z;
    const int tid = threadIdx.x;

    float kk1[9], kk2[9];
    const float l1 = lam[c], l2 = lam[c + 128];
#pragma unroll
    for (int j = 0; j < 9; j++) {
        kk1[j] = dwk[c * 9 + j]         + l1 * gen[((size_t)b * NC2 + c) * 9 + j];
        kk2[j] = dwk[(c + 128) * 9 + j] + l2 * gen[((size_t)b * NC2 + c + 128) * 9 + j];
    }

    const float* u1 = g_u + ((size_t)b * NC2 + c) * NPIX;
    const float* u2 = u1 + (size_t)NHID * NPIX;

    for (int l = tid; l < 34 * 32; l += 256) {
        int rr = l >> 5, p4 = l & 31;
        int gy = r0 + rr - 1;
        float4 a  = make_float4(0.f, 0.f, 0.f, 0.f);
        float4 bb = a;
        if (gy >= 0 && gy < NH) {
            a  = ((const float4*)(u1 + (size_t)gy * NW))[p4];
            bb = ((const float4*)(u2 + (size_t)gy * NW))[p4];
        }
        ((float4*)(s1 + rr * SROW + 4))[p4] = a;
        ((float4*)(s2 + rr * SROW + 4))[p4] = bb;
    }
    if (tid < 68) {   // zero halo columns (x=-1 -> col 3, x=128 -> col 132)
        int rr = tid >> 1, col = (tid & 1) ? 132 : 3;
        s1[rr * SROW + col] = 0.f;
        s2[rr * SROW + col] = 0.f;
    }
    __syncthreads();

    float* gp = g_g + ((size_t)b * NHID + c) * NPIX + (size_t)r0 * NW;
#pragma unroll
    for (int i = 0; i < 16; i++) {
        int lp = tid + i * 256;
        int lr = lp >> 7;
        int xx = lp & 127;
        float a1 = 0.f, a2 = 0.f;
#pragma unroll
        for (int ky = 0; ky < 3; ky++) {
            const float* r1 = s1 + (lr + ky) * SROW + 4 + xx;
            const float* r2 = s2 + (lr + ky) * SROW + 4 + xx;
            a1 += kk1[ky * 3 + 0] * r1[-1] + kk1[ky * 3 + 1] * r1[0] + kk1[ky * 3 + 2] * r1[1];
            a2 += kk2[ky * 3 + 0] * r2[-1] + kk2[ky * 3 + 1] * r2[0] + kk2[ky * 3 + 2] * r2[1];
        }
        float ge = 0.5f * a1 * (1.0f + erff(a1 * 0.7071067811865475f));
        gp[lp] = ge * a2;
    }
}

// ============================================================================
// K3: project_out  out[b][o][p] = sum_c W_out[o][c] * g[b][c][p]
// Tile: 64 out x 128 px, K=128 in two 64-chunks. Channel-packed acc.
// __launch_bounds__(256,4) -> 4 blocks/SM.
// ============================================================================
__global__ __launch_bounds__(256, 4)
void k_proj_out(float* __restrict__ out) {
    extern __shared__ float sm[];
    float* Wt = sm;            // [k=64][o=64] per chunk  16KB
    float* Xs = sm + 4096;     // [k=64][p=128]           32KB

    const int p0  = blockIdx.x * 128;
    const int b   = blockIdx.y;
    const int tid = threadIdx.x;

    const int pg = (tid & 31) * 4;
    const int og = (tid >> 5) * 8;

    unsigned long long acc[4][4];
#pragma unroll
    for (int i = 0; i < 4; i++)
#pragma unroll
        for (int j = 0; j < 4; j++) acc[i][j] = 0ULL;

    const float* wb = Wt + og;
    const float* xp = Xs + pg;

    for (int kc = 0; kc < 2; kc++) {
        const float4* ws = (const float4*)(g_Wt3 + (size_t)kc * 4096);
        for (int l = tid; l < 1024; l += 256) ((float4*)Wt)[l] = ws[l];
        const float* gb = g_g + ((size_t)b * NHID + kc * 64) * NPIX + p0;
        for (int l = tid; l < 64 * 32; l += 256) {
            int k = l >> 5, p4 = l & 31;
            ((float4*)(Xs + k * 128))[p4] =
                ((const float4*)(gb + (size_t)k * NPIX))[p4];
        }
        __syncthreads();

#pragma unroll 8
        for (int k = 0; k < 64; k++) {
            const ulonglong2* wp = (const ulonglong2*)(wb + k * 64);
            ulonglong2 wA = wp[0], wB = wp[1];
            float4 xv = *(const float4*)(xp + k * 128);
            unsigned long long x0 = pk2(xv.x), x1 = pk2(xv.y);
            unsigned long long x2 = pk2(xv.z), x3 = pk2(xv.w);
            fma2(acc[0][0], wA.x, x0); fma2(acc[0][1], wA.x, x1);
            fma2(acc[0][2], wA.x, x2); fma2(acc[0][3], wA.x, x3);
            fma2(acc[1][0], wA.y, x0); fma2(acc[1][1], wA.y, x1);
            fma2(acc[1][2], wA.y, x2); fma2(acc[1][3], wA.y, x3);
            fma2(acc[2][0], wB.x, x0); fma2(acc[2][1], wB.x, x1);
            fma2(acc[2][2], wB.x, x2); fma2(acc[2][3], wB.x, x3);
            fma2(acc[3][0], wB.y, x0); fma2(acc[3][1], wB.y, x1);
            fma2(acc[3][2], wB.y, x2); fma2(acc[3][3], wB.y, x3);
        }
        __syncthreads();
    }

    float* ob = out + ((size_t)(b * NDIM + og)) * NPIX + p0 + pg;
#pragma unroll
    for (int j = 0; j < 4; j++) {
        float2 v0 = up2(acc[j][0]), v1 = up2(acc[j][1]);
        float2 v2 = up2(acc[j][2]), v3 = up2(acc[j][3]);
        *(float4*)(ob + (size_t)(2 * j) * NPIX)     = make_float4(v0.x, v1.x, v2.x, v3.x);
        *(float4*)(ob + (size_t)(2 * j + 1) * NPIX) = make_float4(v0.y, v1.y, v2.y, v3.y);
    }
}

// ============================================================================
extern "C" void kernel_launch(void* const* d_in, const int* in_sizes, int n_in,
                              void* d_out, int out_size) {
    const float* x     = (const float*)d_in[0];
    const float* gen   = (const float*)d_in[1];
    const float* W_in  = (const float*)d_in[2];
    const float* dwk   = (const float*)d_in[3];
    const float* lam   = (const float*)d_in[4];
    const float* W_out = (const float*)d_in[5];
    float* out = (float*)d_out;

    const int smem = 48 * 1024;
    cudaFuncSetAttribute(k_proj_in,  cudaFuncAttributeMaxDynamicSharedMemorySize, smem);
    cudaFuncSetAttribute(k_proj_out, cudaFuncAttributeMaxDynamicSharedMemorySize, smem);

    k_prep<<<64, 256>>>(W_in, W_out);
    k_proj_in<<<dim3(NPIX / 128, NC2 / 64, NB), 256, smem>>>(x);
    k_dwgate<<<dim3(NH / 32, NHID, NB), 256>>>(gen, dwk, lam);
    k_proj_out<<<dim3(NPIX / 128, NB), 256, smem>>>(out);
}